// round 5
// baseline (speedup 1.0000x reference)
#include <cuda_runtime.h>
#include <math.h>

#define Bn 2
#define Ln 256
#define Hn 256
#define Cn 5
#define VOC 511
#define NJ 32
#define KT 16
#define PSTR 257

// Scratch (device globals: no allocations allowed)
__device__ float g_tt[VOC * Hn];        // table @ Wh_w  [511,256]
__device__ float g_a[Bn * Ln * Hn];     // h@(We+Wd) + Wh_b
__device__ float g_bq[Bn * Ln * Hn];    // h@(Ws-Wd)

// ---------------- fused prep: blocks 0..63 -> rel-term GEMM, 64..127 -> a/b
__global__ void __launch_bounds__(256) k_prep(const float* __restrict__ hs,
                                              const float* __restrict__ Whw,
                                              const float* __restrict__ Whb) {
    __shared__ float sh[8 * 1024];
    int t = threadIdx.x;

    if (blockIdx.x < 64) {
        // ---- table_term = table @ Wh_w, table rows computed inline ----
        int vb = blockIdx.x * 8;
        for (int idx = t; idx < 8 * 1024; idx += 256) {
            int v = idx >> 10, k = idx & 1023;
            int vv = vb + v;
            float val = 0.f;
            if (vv < VOC) {
                // div = (float)10000^{(2*(k//2))/1024} computed in f64 (matches np.power->astype(f32))
                double e = (double)(2 * (k >> 1)) * (1.0 / 1024.0);
                double dv = exp2(e * 13.287712379549449);  // log2(10000)
                float ang = (float)vv / (float)dv;         // f32 division like numpy
                val = (k & 1) ? cosf(ang) : sinf(ang);
            }
            sh[idx] = val;
        }
        __syncthreads();
        float acc[8];
#pragma unroll
        for (int v = 0; v < 8; v++) acc[v] = 0.f;
        for (int k = 0; k < 1024; k++) {
            float w = Whw[k * Hn + t];
#pragma unroll
            for (int v = 0; v < 8; v++) acc[v] += sh[v * 1024 + k] * w;
        }
#pragma unroll
        for (int v = 0; v < 8; v++)
            if (vb + v < VOC) g_tt[(vb + v) * Hn + t] = acc[v];
    } else {
        // ---- a = h@(We+Wd)+bias, b = h@(Ws-Wd) ----
        int rb = (blockIdx.x - 64) * 8;  // row index into [B*L]
        for (int idx = t; idx < 8 * Hn; idx += 256) sh[idx] = hs[rb * Hn + idx];
        __syncthreads();
        float aa[8], bb[8];
#pragma unroll
        for (int r = 0; r < 8; r++) { aa[r] = 0.f; bb[r] = 0.f; }
        for (int k = 0; k < Hn; k++) {
            float we = Whw[k * Hn + t];
            float ws = Whw[(Hn + k) * Hn + t];
            float wd = Whw[(2 * Hn + k) * Hn + t];
            float wa = we + wd, wb_ = ws - wd;
#pragma unroll
            for (int r = 0; r < 8; r++) {
                float x = sh[r * Hn + k];
                aa[r] += x * wa;
                bb[r] += x * wb_;
            }
        }
        float bias = Whb[t];
#pragma unroll
        for (int r = 0; r < 8; r++) {
            g_a[(rb + r) * Hn + t]  = aa[r] + bias;
            g_bq[(rb + r) * Hn + t] = bb[r];
        }
    }
}

// ---------------------------------------------------------------- main
__device__ __forceinline__ unsigned long long pack2(float x) {
    unsigned long long r;
    asm("mov.b64 %0, {%1, %1};" : "=l"(r) : "r"(__float_as_uint(x)));
    return r;
}
__device__ __forceinline__ void fma2(unsigned long long& d, unsigned long long a,
                                     unsigned long long b) {
    asm("fma.rn.f32x2 %0, %1, %2, %0;" : "+l"(d) : "l"(a), "l"(b));
}

__global__ void __launch_bounds__(256) k_main(
    const float* __restrict__ hs, const int* __restrict__ mask,
    const float* __restrict__ Whw, const float* __restrict__ Wow,
    const float* __restrict__ Wob, float* __restrict__ out) {
    extern __shared__ float sm[];
    float* s_p   = sm;                    // NJ*PSTR  (p[j][k], padded)
    float* s_wm  = s_p + NJ * PSTR;       // KT*256   Wm k-tile
    float* s_wo  = s_wm + KT * Hn;        // 256*5
    float* s_red = s_wo + Hn * Cn;        // 8*32*5 per-warp partials

    int t = threadIdx.x;
    int tx = t & 31, ty = t >> 5;
    int jb = blockIdx.x * NJ;
    int i  = blockIdx.y;
    int b  = blockIdx.z;
    int jg = tx >> 2;                         // 8 j-groups of 4
    int hbase = ty * 32 + (tx & 3) * 8;       // this thread's 8 h' values

    const float* hb = hs + b * Ln * Hn;
    const float* hi = hb + i * Hn;

    // p[j][k] = h_i[k] * h_j[k]  (coalesced global reads, conflict-free STS)
    for (int idx = t; idx < NJ * Hn; idx += 256) {
        int j = idx >> 8, k = idx & 255;
        s_p[j * PSTR + k] = hi[k] * hb[(jb + j) * Hn + k];
    }
    for (int idx = t; idx < Hn * Cn; idx += 256) s_wo[idx] = Wow[idx];
    __syncthreads();

    unsigned long long acc[4][4];
#pragma unroll
    for (int jj = 0; jj < 4; jj++)
#pragma unroll
        for (int q = 0; q < 4; q++) acc[jj][q] = 0ull;

    const float* Wm = Whw + 3 * Hn * Hn;
    for (int kt = 0; kt < Hn; kt += KT) {
        for (int idx = t; idx < KT * Hn / 4; idx += 256)
            ((float4*)s_wm)[idx] = ((const float4*)(Wm + kt * Hn))[idx];
        __syncthreads();
#pragma unroll
        for (int kk = 0; kk < KT; kk++) {
            const float* wrow = s_wm + kk * Hn + hbase;
            ulonglong2 wA = *(const ulonglong2*)(wrow);
            ulonglong2 wB = *(const ulonglong2*)(wrow + 4);
            int k = kt + kk;
#pragma unroll
            for (int jj = 0; jj < 4; jj++) {
                unsigned long long pp = pack2(s_p[(jg * 4 + jj) * PSTR + k]);
                fma2(acc[jj][0], pp, wA.x);
                fma2(acc[jj][1], pp, wA.y);
                fma2(acc[jj][2], pp, wB.x);
                fma2(acc[jj][3], pp, wB.y);
            }
        }
        __syncthreads();
    }

    // ---------------- epilogue: +a_i +b_j +rel, tanh, @Wo, reduce -------------
    const float* arow = g_a + (b * Ln + i) * Hn + hbase;
    float av[8];
    ((float4*)av)[0] = ((const float4*)arow)[0];
    ((float4*)av)[1] = ((const float4*)(arow + 4))[0];

#pragma unroll
    for (int jj = 0; jj < 4; jj++) {
        int jl = jg * 4 + jj;
        int j = jb + jl;
        int d = j - i;
        d = max(-127, min(127, d)) + 127;
        const float* brow = g_bq + (b * Ln + j) * Hn + hbase;
        const float* rrow = g_tt + d * Hn + hbase;
        float bv[8], rv[8];
        ((float4*)bv)[0] = ((const float4*)brow)[0];
        ((float4*)bv)[1] = ((const float4*)(brow + 4))[0];
        ((float4*)rv)[0] = ((const float4*)rrow)[0];
        ((float4*)rv)[1] = ((const float4*)(rrow + 4))[0];
        float pc[5] = {0.f, 0.f, 0.f, 0.f, 0.f};
#pragma unroll
        for (int u = 0; u < 8; u++) {
            unsigned long long a64 = acc[jj][u >> 1];
            float accv = __uint_as_float((u & 1) ? (unsigned)(a64 >> 32)
                                                 : (unsigned)(a64 & 0xffffffffu));
            float pre = accv + av[u] + bv[u] + rv[u];
            float x = fminf(12.f, fmaxf(-12.f, pre));
            float e = __expf(2.f * x);
            float tn = __fdividef(e - 1.f, e + 1.f);
            int h = hbase + u;
#pragma unroll
            for (int c = 0; c < Cn; c++) pc[c] += tn * s_wo[h * Cn + c];
        }
#pragma unroll
        for (int c = 0; c < Cn; c++) {
            pc[c] += __shfl_xor_sync(0xffffffffu, pc[c], 1);
            pc[c] += __shfl_xor_sync(0xffffffffu, pc[c], 2);
        }
        if ((tx & 3) == 0) {
#pragma unroll
            for (int c = 0; c < Cn; c++) s_red[(ty * NJ + jl) * Cn + c] = pc[c];
        }
    }
    __syncthreads();

    if (t < NJ * Cn) {
        int jl = t / Cn, c = t % Cn;
        float v = 0.f;
#pragma unroll
        for (int w = 0; w < 8; w++) v += s_red[(w * NJ + jl) * Cn + c];
        v += Wob[c];
        int j = jb + jl;
        bool bad = (mask[b * Ln + i] == 0) || (mask[b * Ln + j] == 0);
        float ninf = -__int_as_float(0x7f800000);
        float res = bad ? ninf : (v - ((i > j) ? 1e12f : 0.f));
        out[((b * Cn + c) * Ln + i) * Ln + j] = res;
    }
}

// ---------------------------------------------------------------- launch
extern "C" void kernel_launch(void* const* d_in, const int* in_sizes, int n_in,
                              void* d_out, int out_size) {
    const float* hs   = (const float*)d_in[0];
    const int*   mask = (const int*)d_in[1];
    const float* Whw  = (const float*)d_in[2];
    const float* Whb  = (const float*)d_in[3];
    const float* Wow  = (const float*)d_in[4];
    const float* Wob  = (const float*)d_in[5];
    float* out = (float*)d_out;

    k_prep<<<128, 256>>>(hs, Whw, Whb);

    int smem = (NJ * PSTR + KT * Hn + Hn * Cn + 8 * NJ * Cn) * (int)sizeof(float);
    cudaFuncSetAttribute(k_main, cudaFuncAttributeMaxDynamicSharedMemorySize, smem);
    dim3 g(Ln / NJ, Ln, Bn);
    k_main<<<g, 256, smem>>>(hs, mask, Whw, Wow, Wob, out);
}